// round 10
// baseline (speedup 1.0000x reference)
#include <cuda_runtime.h>
#include <cuda_bf16.h>
#include <cstdint>

#define NROWS 16384
#define CDIM  256
#define KEMB  8192
#define NBATCH 16
#define HW    1024
#define OUT_N (NBATCH * CDIM * HW)   // 4194304

#define NTILES 64                     // 8192 / 128 column tiles
#define MARGIN 4.0e-4f

#define PITCH 144                     // smem row pitch bytes (64 bf16 + 16 pad)
#define BOFFS (128 * PITCH)           // B region offset within a stage (18432)
#define STAGE ((128 + 256) * PITCH)   // 55296 B per K-chunk stage
#define GEMM_SMEM (4 * STAGE)         // 221184 B -> 1 CTA/SM

// ---------------- static device scratch ----------------
__device__ float          g_xt[NROWS * CDIM];    // z transposed [n][c] fp32
__device__ __nv_bfloat16  g_xh[NROWS * CDIM];    // bf16(x)
__device__ __nv_bfloat16  g_eh[KEMB * CDIM];     // bf16(emb)
__device__ int            g_idx[NROWS];
__device__ double         g_partial[4096];
__device__ float4         g_tv[NROWS * NTILES];  // top-4 coarse (-2*dot) per (row,tile)
__device__ int4           g_ti[NROWS * NTILES];  // matching indices

// top-4 running insert, strict < (keeps earliest-seen on ties)
#define TOP4_INSERT(dv, j)                                                    \
    if ((dv) < v3) {                                                          \
        if ((dv) < v2) {                                                      \
            v3 = v2; i3 = i2;                                                 \
            if ((dv) < v1) {                                                  \
                v2 = v1; i2 = i1;                                             \
                if ((dv) < v0) { v1 = v0; i1 = i0; v0 = (dv); i0 = (j); }     \
                else           { v1 = (dv); i1 = (j); }                       \
            } else { v2 = (dv); i2 = (j); }                                   \
        } else { v3 = (dv); i3 = (j); }                                       \
    }

__device__ __forceinline__ uint32_t smem_u32(const void* p) {
    uint32_t a;
    asm("{ .reg .u64 t; cvta.to.shared.u64 t, %1; cvt.u32.u64 %0, t; }" : "=r"(a) : "l"(p));
    return a;
}
__device__ __forceinline__ void ldsm_x4(uint32_t* r, uint32_t addr) {
    asm volatile("ldmatrix.sync.aligned.m8n8.x4.shared.b16 {%0,%1,%2,%3}, [%4];"
                 : "=r"(r[0]), "=r"(r[1]), "=r"(r[2]), "=r"(r[3]) : "r"(addr));
}
#define CP16(dst, src) \
    asm volatile("cp.async.cg.shared.global [%0], [%1], 16;" :: "r"(dst), "l"(src))
#define CP_COMMIT() asm volatile("cp.async.commit_group;" ::: "memory")

#define MMA_BF16(cc, a, b0, b1)                                               \
    asm volatile(                                                             \
        "mma.sync.aligned.m16n8k16.row.col.f32.bf16.bf16.f32 "                \
        "{%0,%1,%2,%3}, {%4,%5,%6,%7}, {%8,%9}, {%0,%1,%2,%3};"               \
        : "+f"((cc)[0]), "+f"((cc)[1]), "+f"((cc)[2]), "+f"((cc)[3])          \
        : "r"((a)[0]), "r"((a)[1]), "r"((a)[2]), "r"((a)[3]),                 \
          "r"(b0), "r"(b1))

// ---------------- K0: transpose z[B,C,HW] -> g_xt / g_xh ----------------
__global__ void k_transpose(const float* __restrict__ z) {
    __shared__ float t[32][33];
    int b = blockIdx.z, c0 = blockIdx.y * 32, hw0 = blockIdx.x * 32;
    int tx = threadIdx.x, ty = threadIdx.y;        // (32, 8)
    #pragma unroll
    for (int i = ty; i < 32; i += 8)
        t[i][tx] = z[((size_t)(b * CDIM + c0 + i)) * HW + hw0 + tx];
    __syncthreads();
    #pragma unroll
    for (int i = ty; i < 32; i += 8) {
        float v = t[tx][i];
        size_t o = ((size_t)(b * HW + hw0 + i)) * CDIM + c0 + tx;
        g_xt[o] = v;
        g_xh[o] = __float2bfloat16(v);
    }
}

// ---------------- K0b: emb -> bf16 ----------------
__global__ void k_ebf(const float* __restrict__ emb) {
    int i = blockIdx.x * 256 + threadIdx.x;        // over KEMB*CDIM/4
    float4 v = reinterpret_cast<const float4*>(emb)[i];
    __nv_bfloat16* o = g_eh + (size_t)i * 4;
    o[0] = __float2bfloat16(v.x); o[1] = __float2bfloat16(v.y);
    o[2] = __float2bfloat16(v.z); o[3] = __float2bfloat16(v.w);
}

// ---------------- K2: coarse bf16 GEMM (CUTLASS-shape) + per-tile top-4 -------
// CTA 128x256, 256 thr = 8 warps (2m x 4n), warp tile 64x64 (128 accum regs).
// K=256 as 4 chunks of 64, ALL preloaded into 4 smem stages via cp.async.
// Fragments double-buffered across k-steps.
__global__ __launch_bounds__(256, 1) void k_gemm_coarse() {
    extern __shared__ __align__(16) char smem[];
    const uint32_t sbase = smem_u32(smem);
    const int tid = threadIdx.x;
    const int rowBase = blockIdx.x * 128;
    const int colBase = blockIdx.y * 256;

    const char* Ag = (const char*)(g_xh + (size_t)rowBase * CDIM);
    const char* Bg = (const char*)(g_eh + (size_t)colBase * CDIM);

    // ---- issue ALL chunk loads up front (4 commit groups) ----
    #pragma unroll
    for (int ch = 0; ch < 4; ch++) {
        const uint32_t dst = sbase + ch * STAGE;
        #pragma unroll
        for (int i = 0; i < 4; i++) {              // A: 128 rows x 8 granules
            int t = tid + i * 256;
            int r = t >> 3, gr = t & 7;
            CP16(dst + r * PITCH + gr * 16,
                 Ag + ((size_t)r * CDIM + ch * 64 + gr * 8) * 2);
        }
        #pragma unroll
        for (int i = 0; i < 8; i++) {              // B: 256 rows x 8 granules
            int t = tid + i * 256;
            int r = t >> 3, gr = t & 7;
            CP16(dst + BOFFS + r * PITCH + gr * 16,
                 Bg + ((size_t)r * CDIM + ch * 64 + gr * 8) * 2);
        }
        CP_COMMIT();
    }

    const int lane = tid & 31, wid = tid >> 5;
    const int g = lane >> 2, m4 = lane & 3;
    const int mw = wid >> 2, nw = wid & 3;         // 2 m-groups x 4 n-groups

    float c[4][8][4];
    #pragma unroll
    for (int mt = 0; mt < 4; mt++)
        #pragma unroll
        for (int nt = 0; nt < 8; nt++)
            #pragma unroll
            for (int q = 0; q < 4; q++) c[mt][nt][q] = 0.0f;

    // per-lane ldsm offsets within a stage
    const uint32_t aoff = (uint32_t)((mw * 64 + (lane & 15)) * PITCH
                                     + ((lane >> 4) & 1) * 16);
    const uint32_t boff = (uint32_t)(BOFFS
                                     + (nw * 64 + ((lane >> 4) & 1) * 8 + (lane & 7)) * PITCH
                                     + ((lane >> 3) & 1) * 16);

    #pragma unroll
    for (int ch = 0; ch < 4; ch++) {
        if (ch == 0)      asm volatile("cp.async.wait_group 3;" ::: "memory");
        else if (ch == 1) asm volatile("cp.async.wait_group 2;" ::: "memory");
        else if (ch == 2) asm volatile("cp.async.wait_group 1;" ::: "memory");
        else              asm volatile("cp.async.wait_group 0;" ::: "memory");
        __syncthreads();

        const uint32_t bA = sbase + ch * STAGE + aoff;
        const uint32_t bB = sbase + ch * STAGE + boff;

        uint32_t a[2][4][4], b[2][4][4];
        #pragma unroll
        for (int mt = 0; mt < 4; mt++) ldsm_x4(a[0][mt], bA + mt * 16 * PITCH);
        #pragma unroll
        for (int np = 0; np < 4; np++) ldsm_x4(b[0][np], bB + np * 16 * PITCH);

        #pragma unroll
        for (int ks = 0; ks < 4; ks++) {
            const int cur = ks & 1, nxt = cur ^ 1;
            if (ks < 3) {
                const uint32_t ko = (ks + 1) * 32;
                #pragma unroll
                for (int mt = 0; mt < 4; mt++)
                    ldsm_x4(a[nxt][mt], bA + mt * 16 * PITCH + ko);
                #pragma unroll
                for (int np = 0; np < 4; np++)
                    ldsm_x4(b[nxt][np], bB + np * 16 * PITCH + ko);
            }
            #pragma unroll
            for (int mt = 0; mt < 4; mt++)
                #pragma unroll
                for (int np = 0; np < 4; np++) {
                    MMA_BF16(c[mt][np * 2],     a[cur][mt], b[cur][np][0], b[cur][np][1]);
                    MMA_BF16(c[mt][np * 2 + 1], a[cur][mt], b[cur][np][2], b[cur][np][3]);
                }
        }
    }
    // mainloop done. All ldsm of stage0 finished before chunk-1's barrier, so
    // stage0 can be reused for the reduction without another sync here.

    float* redv = reinterpret_cast<float*>(smem);           // 2048 floats
    int*   redi = reinterpret_cast<int*>(smem) + 2048;      // 2048 ints (16KB total)

    // ---- register epilogue: per-thread top-4 per local row, quad merge ----
    // row = mw*64 + mt*16 + hf*8 + g ; col = colBase + nw*64 + nt*8 + m4*2 + e
    #pragma unroll
    for (int mt = 0; mt < 4; mt++)
        #pragma unroll
        for (int hf = 0; hf < 2; hf++) {
            float v0 = 1e30f, v1 = 1e30f, v2 = 1e30f, v3 = 1e30f;
            int   i0 = 0,     i1 = 0,     i2 = 0,     i3 = 0;
            #pragma unroll
            for (int nt = 0; nt < 8; nt++)
                #pragma unroll
                for (int e = 0; e < 2; e++) {
                    float dv = -2.0f * c[mt][nt][hf * 2 + e];
                    int j = colBase + nw * 64 + nt * 8 + m4 * 2 + e;
                    TOP4_INSERT(dv, j);
                }
            #pragma unroll
            for (int s = 1; s <= 2; s <<= 1) {
                float w0 = __shfl_xor_sync(0xffffffffu, v0, s);
                float w1 = __shfl_xor_sync(0xffffffffu, v1, s);
                float w2 = __shfl_xor_sync(0xffffffffu, v2, s);
                float w3 = __shfl_xor_sync(0xffffffffu, v3, s);
                int   q0 = __shfl_xor_sync(0xffffffffu, i0, s);
                int   q1 = __shfl_xor_sync(0xffffffffu, i1, s);
                int   q2 = __shfl_xor_sync(0xffffffffu, i2, s);
                int   q3 = __shfl_xor_sync(0xffffffffu, i3, s);
                TOP4_INSERT(w0, q0); TOP4_INSERT(w1, q1);
                TOP4_INSERT(w2, q2); TOP4_INSERT(w3, q3);
            }
            if (m4 == 0) {
                int row = mw * 64 + mt * 16 + hf * 8 + g;
                int t128 = nw >> 1, sub = nw & 1;
                int base = (row * 2 + t128) * 8 + sub * 4;
                redv[base + 0] = v0; redv[base + 1] = v1;
                redv[base + 2] = v2; redv[base + 3] = v3;
                redi[base + 0] = i0; redi[base + 1] = i1;
                redi[base + 2] = i2; redi[base + 3] = i3;
            }
        }
    __syncthreads();

    // ---- merge 2 warp halves -> per-(row, 128-col-tile) top-4 ----
    {
        int row = tid >> 1, t128 = tid & 1;
        float v0 = 1e30f, v1 = 1e30f, v2 = 1e30f, v3 = 1e30f;
        int   i0 = 0,     i1 = 0,     i2 = 0,     i3 = 0;
        #pragma unroll
        for (int e = 0; e < 8; e++) {
            float dv = redv[tid * 8 + e];
            int j = redi[tid * 8 + e];
            TOP4_INSERT(dv, j);
        }
        int n = rowBase + row;
        g_tv[(size_t)n * NTILES + blockIdx.y * 2 + t128] = make_float4(v0, v1, v2, v3);
        g_ti[(size_t)n * NTILES + blockIdx.y * 2 + t128] = make_int4(i0, i1, i2, i3);
    }
}

// ---------------- K3: exact rescore (S computed in-kernel, bit-identical) -----
// One warp per row; 256 stored entries; rescore all within MARGIN of coarse min
// with the EXACT fp32 chain; lexicographic (d, j) = first-index tie-break.
__global__ __launch_bounds__(128) void k_rescore(const float* __restrict__ emb,
                                                 float* __restrict__ idx_out_f) {
    int wid = threadIdx.x >> 5, lid = threadIdx.x & 31;
    int n = blockIdx.x * 4 + wid;
    const float4* tv = g_tv + (size_t)n * NTILES;
    const int4*   ti = g_ti + (size_t)n * NTILES;

    const float* xr = g_xt + (size_t)n * CDIM;

    // |x|^2: same per-lane element mapping + shfl_down order as the old
    // k_rownorm -> bit-identical S.
    double acc = 0.0;
    #pragma unroll
    for (int h = 0; h < 2; h++) {
        float4 v = *reinterpret_cast<const float4*>(&xr[h * 128 + lid * 4]);
        acc += (double)__fmul_rn(v.x, v.x);
        acc += (double)__fmul_rn(v.y, v.y);
        acc += (double)__fmul_rn(v.z, v.z);
        acc += (double)__fmul_rn(v.w, v.w);
    }
    #pragma unroll
    for (int off = 16; off > 0; off >>= 1)
        acc += __shfl_down_sync(0xffffffffu, acc, off);
    const float S = __shfl_sync(0xffffffffu, (float)acc, 0);

    float ev[8]; int ei[8];
    #pragma unroll
    for (int q = 0; q < 8; q++) {
        int e = q * 32 + lid;                      // entry 0..255
        float4 v4 = tv[e >> 2];
        int4   i4 = ti[e >> 2];
        int rk = e & 3;
        ev[q] = (rk == 0) ? v4.x : (rk == 1) ? v4.y : (rk == 2) ? v4.z : v4.w;
        ei[q] = (rk == 0) ? i4.x : (rk == 1) ? i4.y : (rk == 2) ? i4.z : i4.w;
    }
    float m = 1e30f;
    #pragma unroll
    for (int q = 0; q < 8; q++) m = fminf(m, ev[q]);
    #pragma unroll
    for (int off = 16; off > 0; off >>= 1)
        m = fminf(m, __shfl_xor_sync(0xffffffffu, m, off));

    float best = 1e30f; int bj = 0x7fffffff;
    #pragma unroll
    for (int q = 0; q < 8; q++) {
        if (ev[q] <= m + MARGIN) {
            int j = ei[q];
            const float* er = emb + (size_t)j * CDIM;
            float dot = 0.0f;
            #pragma unroll 8
            for (int k = 0; k < CDIM; k++)
                dot = __fmaf_rn(xr[k], er[k], dot);
            float d = __fadd_rn(S, -__fmul_rn(2.0f, dot));
            if (d < best || (d == best && j < bj)) { best = d; bj = j; }
        }
    }
    #pragma unroll
    for (int off = 16; off > 0; off >>= 1) {
        float ov = __shfl_xor_sync(0xffffffffu, best, off);
        int   oj = __shfl_xor_sync(0xffffffffu, bj,   off);
        if (ov < best || (ov == best && oj < bj)) { best = ov; bj = oj; }
    }
    if (lid == 0) {
        g_idx[n] = bj;
        idx_out_f[n] = (float)bj;
    }
}

// ---------------- K4: gather + straight-through output + loss partials --------
__global__ void k_output(const float* __restrict__ emb, float* __restrict__ out) {
    __shared__ float tile[32][33];
    __shared__ double sred[256];
    int b = blockIdx.z, c0 = blockIdx.y * 32, hw0 = blockIdx.x * 32;
    int tx = threadIdx.x, ty = threadIdx.y;        // (32, 8)
    double acc = 0.0;
    #pragma unroll
    for (int i = ty; i < 32; i += 8) {
        int n = b * HW + hw0 + i;
        int id = g_idx[n];
        float zv = g_xt[(size_t)n * CDIM + c0 + tx];
        float qv = emb[(size_t)id * CDIM + c0 + tx];
        float t  = __fsub_rn(qv, zv);
        float o  = __fadd_rn(zv, t);
        tile[i][tx] = o;
        acc += (double)__fmul_rn(t, t);
    }
    __syncthreads();
    #pragma unroll
    for (int i = ty; i < 32; i += 8)
        out[((size_t)(b * CDIM + c0 + i)) * HW + hw0 + tx] = tile[tx][i];

    int tid = ty * 32 + tx;
    sred[tid] = acc;
    __syncthreads();
    for (int s = 128; s > 0; s >>= 1) {
        if (tid < s) sred[tid] += sred[tid + s];
        __syncthreads();
    }
    if (tid == 0)
        g_partial[blockIdx.x + 32 * (blockIdx.y + 8 * blockIdx.z)] = sred[0];
}

// ---------------- K5: final loss reduce ----------------
__global__ void k_loss(float* __restrict__ out_loss) {
    __shared__ double sred[256];
    int tid = threadIdx.x;
    double acc = 0.0;
    for (int q = tid; q < 4096; q += 256) acc += g_partial[q];
    sred[tid] = acc;
    __syncthreads();
    for (int s = 128; s > 0; s >>= 1) {
        if (tid < s) sred[tid] += sred[tid + s];
        __syncthreads();
    }
    if (tid == 0) {
        float m = (float)(sred[0] / (double)OUT_N);
        out_loss[0] = __fadd_rn(m, __fmul_rn(0.25f, m));
    }
}

// ---------------- entry ----------------
extern "C" void kernel_launch(void* const* d_in, const int* in_sizes, int n_in,
                              void* d_out, int out_size) {
    const float* z   = (const float*)d_in[0];
    const float* emb = (const float*)d_in[1];
    float* out    = (float*)d_out;
    float* loss_p = out + OUT_N;
    float* idx_p  = out + OUT_N + 1;

    cudaFuncSetAttribute(k_gemm_coarse,
                         cudaFuncAttributeMaxDynamicSharedMemorySize, GEMM_SMEM);

    k_transpose<<<dim3(32, 8, 16), dim3(32, 8)>>>(z);
    k_ebf<<<(KEMB * CDIM / 4) / 256, 256>>>(emb);
    k_gemm_coarse<<<dim3(NROWS / 128, KEMB / 256), 256, GEMM_SMEM>>>();
    k_rescore<<<NROWS / 4, 128>>>(emb, idx_p);
    k_output<<<dim3(32, 8, 16), dim3(32, 8)>>>(emb, out);
    k_loss<<<1, 256>>>(loss_p);
}

// round 11
// speedup vs baseline: 1.3031x; 1.3031x over previous
#include <cuda_runtime.h>
#include <cuda_fp16.h>
#include <cstdint>

#define NROWS 16384
#define CDIM  256
#define KEMB  8192
#define NBATCH 16
#define HW    1024
#define OUT_N (NBATCH * CDIM * HW)   // 4194304

#define NTILES 64                     // 8192 / 128 column tiles
#define MARGIN 6.0e-4f

#define APITCH 144                    // smem row pitch (bytes): 64 fp16 + 16B pad
#define ABUF   (128 * APITCH)         // 18432 B (A chunk: 128 rows)
#define BBUF   (128 * APITCH)         // 18432 B (B chunk: 128 codewords)
#define STAGE  (ABUF + BBUF)          // 36864 B
#define GEMM_SMEM (2 * STAGE)         // 73728 B -> 2 CTAs/SM
#define RPW 17                        // reduction smem pitch (words)

// ---------------- static device scratch ----------------
__device__ float   g_xt[NROWS * CDIM];    // z transposed [n][c] fp32
__device__ __half  g_xh[NROWS * CDIM];    // fp16(x)
__device__ __half  g_eh[KEMB * CDIM];     // fp16(emb)
__device__ float   g_rownorm[NROWS];
__device__ int     g_idx[NROWS];
__device__ double  g_partial[4096];
__device__ float4  g_tv[NROWS * NTILES];  // top-4 coarse (-2*dot) per (row,tile)
__device__ int4    g_ti[NROWS * NTILES];  // matching indices

// top-4 running insert, strict < (keeps earliest-seen on ties)
#define TOP4_INSERT(dv, j)                                                    \
    if ((dv) < v3) {                                                          \
        if ((dv) < v2) {                                                      \
            v3 = v2; i3 = i2;                                                 \
            if ((dv) < v1) {                                                  \
                v2 = v1; i2 = i1;                                             \
                if ((dv) < v0) { v1 = v0; i1 = i0; v0 = (dv); i0 = (j); }     \
                else           { v1 = (dv); i1 = (j); }                       \
            } else { v2 = (dv); i2 = (j); }                                   \
        } else { v3 = (dv); i3 = (j); }                                       \
    }

__device__ __forceinline__ uint32_t smem_u32(const void* p) {
    uint32_t a;
    asm("{ .reg .u64 t; cvta.to.shared.u64 t, %1; cvt.u32.u64 %0, t; }" : "=r"(a) : "l"(p));
    return a;
}
__device__ __forceinline__ void ldsm_x4(uint32_t& r0, uint32_t& r1, uint32_t& r2,
                                        uint32_t& r3, uint32_t addr) {
    asm volatile("ldmatrix.sync.aligned.m8n8.x4.shared.b16 {%0,%1,%2,%3}, [%4];"
                 : "=r"(r0), "=r"(r1), "=r"(r2), "=r"(r3) : "r"(addr));
}
#define CP16(dst, src) \
    asm volatile("cp.async.cg.shared.global [%0], [%1], 16;" :: "r"(dst), "l"(src))
#define CP_COMMIT() asm volatile("cp.async.commit_group;" ::: "memory")

// fp16-accumulate MMA: D/C are 2x b32 regs (4 halves)
#define MMA_F16(cc, a, b0, b1)                                                \
    asm volatile(                                                             \
        "mma.sync.aligned.m16n8k16.row.col.f16.f16.f16.f16 "                  \
        "{%0,%1}, {%2,%3,%4,%5}, {%6,%7}, {%0,%1};"                           \
        : "+r"((cc)[0]), "+r"((cc)[1])                                        \
        : "r"((a)[0]), "r"((a)[1]), "r"((a)[2]), "r"((a)[3]),                 \
          "r"(b0), "r"(b1))

// ---------------- K0: transpose z[B,C,HW] -> g_xt / g_xh ----------------
__global__ void k_transpose(const float* __restrict__ z) {
    __shared__ float t[32][33];
    int b = blockIdx.z, c0 = blockIdx.y * 32, hw0 = blockIdx.x * 32;
    int tx = threadIdx.x, ty = threadIdx.y;        // (32, 8)
    #pragma unroll
    for (int i = ty; i < 32; i += 8)
        t[i][tx] = z[((size_t)(b * CDIM + c0 + i)) * HW + hw0 + tx];
    __syncthreads();
    #pragma unroll
    for (int i = ty; i < 32; i += 8) {
        float v = t[tx][i];
        size_t o = ((size_t)(b * HW + hw0 + i)) * CDIM + c0 + tx;
        g_xt[o] = v;
        g_xh[o] = __float2half(v);
    }
}

// ---------------- K0b: emb -> fp16 ----------------
__global__ void k_ehf(const float* __restrict__ emb) {
    int i = blockIdx.x * 256 + threadIdx.x;        // over KEMB*CDIM/4
    float4 v = reinterpret_cast<const float4*>(emb)[i];
    __half* o = g_eh + (size_t)i * 4;
    o[0] = __float2half(v.x); o[1] = __float2half(v.y);
    o[2] = __float2half(v.z); o[3] = __float2half(v.w);
}

// ---------------- K1: |x|^2 per row ----------------
__global__ void k_rownorm() {
    int row  = blockIdx.x * 8 + threadIdx.y;       // (32, 8)
    int lane = threadIdx.x;
    const float* r = g_xt + (size_t)row * CDIM;
    double acc = 0.0;
    #pragma unroll
    for (int h = 0; h < 2; h++) {
        float4 v = *reinterpret_cast<const float4*>(&r[h * 128 + lane * 4]);
        acc += (double)__fmul_rn(v.x, v.x);
        acc += (double)__fmul_rn(v.y, v.y);
        acc += (double)__fmul_rn(v.z, v.z);
        acc += (double)__fmul_rn(v.w, v.w);
    }
    #pragma unroll
    for (int off = 16; off > 0; off >>= 1)
        acc += __shfl_down_sync(0xffffffffu, acc, off);
    if (lane == 0) g_rownorm[row] = (float)acc;
}

// ---------------- K2: coarse fp16 mma.sync GEMM + per-tile top-4 ----------------
// CTA: 128 rows x 128 cols. K=256 streamed as 4 chunks of 64, 2-stage cp.async
// double buffer (74KB smem -> 2 CTAs/SM). 512 thr = 16 warps (4m x 4n),
// warp tile 32x32, fp16 accumulators (16 regs).
__global__ __launch_bounds__(512, 2) void k_gemm_coarse() {
    extern __shared__ __align__(16) char smem[];
    const uint32_t sbase = smem_u32(smem);
    const int tid = threadIdx.x;
    const int rowBase = blockIdx.x * 128;
    const int colBase = blockIdx.y * 128;

    const char* Ag = (const char*)(g_xh + (size_t)rowBase * CDIM);
    const char* Bg = (const char*)(g_eh + (size_t)colBase * CDIM);

    // per-thread cp.async coords: 1024 16B transfers per operand per chunk
    const int ldr = tid >> 3, ldc = tid & 7;       // row 0..63 (x2 via it), col16 0..7

    auto load_chunk = [&](int ch) {
        const uint32_t dA = sbase + (uint32_t)((ch & 1) * STAGE);
        const uint32_t dB = dA + ABUF;
        #pragma unroll
        for (int it = 0; it < 2; it++) {
            int r = ldr + it * 64;
            uint32_t so = (uint32_t)(r * APITCH + ldc * 16);
            size_t  go = ((size_t)r * CDIM + ch * 64 + ldc * 8) * 2;
            CP16(dA + so, Ag + go);
            CP16(dB + so, Bg + go);
        }
        CP_COMMIT();
    };

    const int lane = tid & 31, wid = tid >> 5;
    const int g = lane >> 2, m4 = lane & 3;
    const int mw = wid >> 2, nw = wid & 3;

    uint32_t c[2][4][2];
    #pragma unroll
    for (int mt = 0; mt < 2; mt++)
        #pragma unroll
        for (int nt = 0; nt < 4; nt++) { c[mt][nt][0] = 0u; c[mt][nt][1] = 0u; }

    // ldmatrix per-lane offsets (within a stage)
    const uint32_t aoff = (uint32_t)((mw * 32 + (lane & 15)) * APITCH
                                     + ((lane >> 4) & 1) * 16);
    const uint32_t boff = (uint32_t)(ABUF
                                     + (nw * 32 + ((lane >> 4) & 1) * 8 + (lane & 7)) * APITCH
                                     + ((lane >> 3) & 1) * 16);

    auto compute_chunk = [&](int ch) {
        const uint32_t sg = sbase + (uint32_t)((ch & 1) * STAGE);
        const uint32_t bA = sg + aoff;
        const uint32_t bB = sg + boff;
        #pragma unroll
        for (int ks = 0; ks < 4; ks++) {
            const uint32_t ko = ks * 32;
            uint32_t a[2][4], b[2][4];
            ldsm_x4(a[0][0], a[0][1], a[0][2], a[0][3], bA + ko);
            ldsm_x4(a[1][0], a[1][1], a[1][2], a[1][3], bA + 16 * APITCH + ko);
            ldsm_x4(b[0][0], b[0][1], b[0][2], b[0][3], bB + ko);
            ldsm_x4(b[1][0], b[1][1], b[1][2], b[1][3], bB + 16 * APITCH + ko);
            #pragma unroll
            for (int mt = 0; mt < 2; mt++)
                #pragma unroll
                for (int ntp = 0; ntp < 2; ntp++) {
                    MMA_F16(c[mt][ntp * 2],     a[mt], b[ntp][0], b[ntp][1]);
                    MMA_F16(c[mt][ntp * 2 + 1], a[mt], b[ntp][2], b[ntp][3]);
                }
        }
    };

    // 2-stage pipeline over 4 K-chunks
    load_chunk(0);
    load_chunk(1);
    asm volatile("cp.async.wait_group 1;" ::: "memory");
    __syncthreads();
    compute_chunk(0);
    __syncthreads();
    load_chunk(2);
    asm volatile("cp.async.wait_group 1;" ::: "memory");
    __syncthreads();
    compute_chunk(1);
    __syncthreads();
    load_chunk(3);
    asm volatile("cp.async.wait_group 1;" ::: "memory");
    __syncthreads();
    compute_chunk(2);
    __syncthreads();
    asm volatile("cp.async.wait_group 0;" ::: "memory");
    __syncthreads();
    compute_chunk(3);
    __syncthreads();   // buffers dead; reuse smem for reduction

    float* redv = reinterpret_cast<float*>(smem);
    int*   redi = reinterpret_cast<int*>(smem) + 128 * RPW;

    // ---- register epilogue: per-thread top-4 per local row, quad merge ----
    // c[mt][nt][hf] holds halves for (row = mw*32+mt*16+hf*8+g, cols m4*2, m4*2+1)
    #pragma unroll
    for (int lr = 0; lr < 4; lr++) {
        const int mt = lr >> 1, hf = lr & 1;
        float v0 = 1e30f, v1 = 1e30f, v2 = 1e30f, v3 = 1e30f;
        int   i0 = 0,     i1 = 0,     i2 = 0,     i3 = 0;
        #pragma unroll
        for (int nt = 0; nt < 4; nt++) {
            float2 f = __half22float2(*reinterpret_cast<__half2*>(&c[mt][nt][hf]));
            int j0 = colBase + nw * 32 + nt * 8 + m4 * 2;
            float dv0 = -2.0f * f.x;
            float dv1 = -2.0f * f.y;
            TOP4_INSERT(dv0, j0);
            TOP4_INSERT(dv1, j0 + 1);
        }
        #pragma unroll
        for (int s = 1; s <= 2; s <<= 1) {
            float w0 = __shfl_xor_sync(0xffffffffu, v0, s);
            float w1 = __shfl_xor_sync(0xffffffffu, v1, s);
            float w2 = __shfl_xor_sync(0xffffffffu, v2, s);
            float w3 = __shfl_xor_sync(0xffffffffu, v3, s);
            int   q0 = __shfl_xor_sync(0xffffffffu, i0, s);
            int   q1 = __shfl_xor_sync(0xffffffffu, i1, s);
            int   q2 = __shfl_xor_sync(0xffffffffu, i2, s);
            int   q3 = __shfl_xor_sync(0xffffffffu, i3, s);
            TOP4_INSERT(w0, q0); TOP4_INSERT(w1, q1);
            TOP4_INSERT(w2, q2); TOP4_INSERT(w3, q3);
        }
        if (m4 == 0) {
            int row = mw * 32 + mt * 16 + hf * 8 + g;
            int base = row * RPW + nw * 4;
            redv[base + 0] = v0; redv[base + 1] = v1;
            redv[base + 2] = v2; redv[base + 3] = v3;
            redi[base + 0] = i0; redi[base + 1] = i1;
            redi[base + 2] = i2; redi[base + 3] = i3;
        }
    }
    __syncthreads();

    // ---- merge 4 warp-column ranges -> per-row top-4 over 128 cols ----
    if (tid < 128) {
        float v0 = 1e30f, v1 = 1e30f, v2 = 1e30f, v3 = 1e30f;
        int   i0 = 0,     i1 = 0,     i2 = 0,     i3 = 0;
        #pragma unroll
        for (int e = 0; e < 16; e++) {
            float dv = redv[tid * RPW + e];
            int j = redi[tid * RPW + e];
            TOP4_INSERT(dv, j);
        }
        int n = rowBase + tid;
        g_tv[(size_t)n * NTILES + blockIdx.y] = make_float4(v0, v1, v2, v3);
        g_ti[(size_t)n * NTILES + blockIdx.y] = make_int4(i0, i1, i2, i3);
    }
}

// ---------------- K3: exact rescore of near-min candidates ----------------
// One warp per row; 256 stored entries; rescore all within MARGIN of coarse min
// with the EXACT fp32 chain; lexicographic (d, j) = first-index tie-break.
__global__ __launch_bounds__(128) void k_rescore(const float* __restrict__ emb,
                                                 float* __restrict__ idx_out_f) {
    int wid = threadIdx.x >> 5, lid = threadIdx.x & 31;
    int n = blockIdx.x * 4 + wid;
    const float4* tv = g_tv + (size_t)n * NTILES;
    const int4*   ti = g_ti + (size_t)n * NTILES;

    float ev[8]; int ei[8];
    #pragma unroll
    for (int q = 0; q < 8; q++) {
        int e = q * 32 + lid;                      // entry 0..255
        float4 v4 = tv[e >> 2];
        int4   i4 = ti[e >> 2];
        int rk = e & 3;
        ev[q] = (rk == 0) ? v4.x : (rk == 1) ? v4.y : (rk == 2) ? v4.z : v4.w;
        ei[q] = (rk == 0) ? i4.x : (rk == 1) ? i4.y : (rk == 2) ? i4.z : i4.w;
    }
    float m = 1e30f;
    #pragma unroll
    for (int q = 0; q < 8; q++) m = fminf(m, ev[q]);
    #pragma unroll
    for (int off = 16; off > 0; off >>= 1)
        m = fminf(m, __shfl_xor_sync(0xffffffffu, m, off));

    const float S = g_rownorm[n];
    const float* xr = g_xt + (size_t)n * CDIM;
    float best = 1e30f; int bj = 0x7fffffff;
    #pragma unroll
    for (int q = 0; q < 8; q++) {
        if (ev[q] <= m + MARGIN) {
            int j = ei[q];
            const float* er = emb + (size_t)j * CDIM;
            float dot = 0.0f;
            #pragma unroll 8
            for (int k = 0; k < CDIM; k++)
                dot = __fmaf_rn(xr[k], er[k], dot);
            float d = __fadd_rn(S, -__fmul_rn(2.0f, dot));
            if (d < best || (d == best && j < bj)) { best = d; bj = j; }
        }
    }
    #pragma unroll
    for (int off = 16; off > 0; off >>= 1) {
        float ov = __shfl_xor_sync(0xffffffffu, best, off);
        int   oj = __shfl_xor_sync(0xffffffffu, bj,   off);
        if (ov < best || (ov == best && oj < bj)) { best = ov; bj = oj; }
    }
    if (lid == 0) {
        g_idx[n] = bj;
        idx_out_f[n] = (float)bj;
    }
}

// ---------------- K4: gather + straight-through output + loss partials --------
__global__ void k_output(const float* __restrict__ emb, float* __restrict__ out) {
    __shared__ float tile[32][33];
    __shared__ double sred[256];
    int b = blockIdx.z, c0 = blockIdx.y * 32, hw0 = blockIdx.x * 32;
    int tx = threadIdx.x, ty = threadIdx.y;        // (32, 8)
    double acc = 0.0;
    #pragma unroll
    for (int i = ty; i < 32; i += 8) {
        int n = b * HW + hw0 + i;
        int id = g_idx[n];
        float zv = g_xt[(size_t)n * CDIM + c0 + tx];
        float qv = emb[(size_t)id * CDIM + c0 + tx];
        float t  = __fsub_rn(qv, zv);
        float o  = __fadd_rn(zv, t);
        tile[i][tx] = o;
        acc += (double)__fmul_rn(t, t);
    }
    __syncthreads();
    #pragma unroll
    for (int i = ty; i < 32; i += 8)
        out[((size_t)(b * CDIM + c0 + i)) * HW + hw0 + tx] = tile[tx][i];

    int tid = ty * 32 + tx;
    sred[tid] = acc;
    __syncthreads();
    for (int s = 128; s > 0; s >>= 1) {
        if (tid < s) sred[tid] += sred[tid + s];
        __syncthreads();
    }
    if (tid == 0)
        g_partial[blockIdx.x + 32 * (blockIdx.y + 8 * blockIdx.z)] = sred[0];
}

// ---------------- K5: final loss reduce ----------------
__global__ void k_loss(float* __restrict__ out_loss) {
    __shared__ double sred[256];
    int tid = threadIdx.x;
    double acc = 0.0;
    for (int q = tid; q < 4096; q += 256) acc += g_partial[q];
    sred[tid] = acc;
    __syncthreads();
    for (int s = 128; s > 0; s >>= 1) {
        if (tid < s) sred[tid] += sred[tid + s];
        __syncthreads();
    }
    if (tid == 0) {
        float m = (float)(sred[0] / (double)OUT_N);
        out_loss[0] = __fadd_rn(m, __fmul_rn(0.25f, m));
    }
}

// ---------------- entry ----------------
extern "C" void kernel_launch(void* const* d_in, const int* in_sizes, int n_in,
                              void* d_out, int out_size) {
    const float* z   = (const float*)d_in[0];
    const float* emb = (const float*)d_in[1];
    float* out    = (float*)d_out;
    float* loss_p = out + OUT_N;
    float* idx_p  = out + OUT_N + 1;

    cudaFuncSetAttribute(k_gemm_coarse,
                         cudaFuncAttributeMaxDynamicSharedMemorySize, GEMM_SMEM);

    k_transpose<<<dim3(32, 8, 16), dim3(32, 8)>>>(z);
    k_ehf<<<(KEMB * CDIM / 4) / 256, 256>>>(emb);
    k_rownorm<<<NROWS / 8, dim3(32, 8)>>>();
    k_gemm_coarse<<<dim3(NROWS / 128, KEMB / 128), 512, GEMM_SMEM>>>();
    k_rescore<<<NROWS / 4, 128>>>(emb, idx_p);
    k_output<<<dim3(32, 8, 16), dim3(32, 8)>>>(emb, out);
    k_loss<<<1, 256>>>(loss_p);
}

// round 12
// speedup vs baseline: 1.6680x; 1.2800x over previous
#include <cuda_runtime.h>
#include <cuda_fp16.h>
#include <cstdint>

#define NROWS 16384
#define CDIM  256
#define KEMB  8192
#define NBATCH 16
#define HW    1024
#define OUT_N (NBATCH * CDIM * HW)   // 4194304

#define NTILES 64                     // 8192 / 128 column tiles
#define MARGIN 6.0e-4f

#define APITCH 144                    // smem row pitch (bytes): 64 fp16 + 16B pad
#define ABUF   (128 * APITCH)
#define BBUF   (128 * APITCH)
#define STAGE  (ABUF + BBUF)          // 36864 B
#define GEMM_SMEM (2 * STAGE)         // 73728 B -> 2 CTAs/SM
#define RPW 17                        // reduction smem pitch (words)

// ---------------- static device scratch ----------------
__device__ float   g_xt[NROWS * CDIM];    // z transposed [n][c] fp32
__device__ __half  g_xh[NROWS * CDIM];    // fp16(x)
__device__ __half  g_eh[KEMB * CDIM];     // fp16(emb)
__device__ float   g_rownorm[NROWS];
__device__ int     g_idx[NROWS];
__device__ double  g_partial[512];
__device__ float4  g_tv[NROWS * NTILES];  // top-4 coarse (-2*dot) per (row,tile)
__device__ int4    g_ti[NROWS * NTILES];  // matching indices

// top-4 running insert, strict < (keeps earliest-seen on ties)
#define TOP4_INSERT(dv, j)                                                    \
    if ((dv) < v3) {                                                          \
        if ((dv) < v2) {                                                      \
            v3 = v2; i3 = i2;                                                 \
            if ((dv) < v1) {                                                  \
                v2 = v1; i2 = i1;                                             \
                if ((dv) < v0) { v1 = v0; i1 = i0; v0 = (dv); i0 = (j); }     \
                else           { v1 = (dv); i1 = (j); }                       \
            } else { v2 = (dv); i2 = (j); }                                   \
        } else { v3 = (dv); i3 = (j); }                                       \
    }

__device__ __forceinline__ uint32_t smem_u32(const void* p) {
    uint32_t a;
    asm("{ .reg .u64 t; cvta.to.shared.u64 t, %1; cvt.u32.u64 %0, t; }" : "=r"(a) : "l"(p));
    return a;
}
__device__ __forceinline__ void ldsm_x4(uint32_t& r0, uint32_t& r1, uint32_t& r2,
                                        uint32_t& r3, uint32_t addr) {
    asm volatile("ldmatrix.sync.aligned.m8n8.x4.shared.b16 {%0,%1,%2,%3}, [%4];"
                 : "=r"(r0), "=r"(r1), "=r"(r2), "=r"(r3) : "r"(addr));
}
#define CP16(dst, src) \
    asm volatile("cp.async.cg.shared.global [%0], [%1], 16;" :: "r"(dst), "l"(src))
#define CP_COMMIT() asm volatile("cp.async.commit_group;" ::: "memory")

// fp16-accumulate MMA: D/C are 2x b32 regs (4 halves)
#define MMA_F16(cc, a, b0, b1)                                                \
    asm volatile(                                                             \
        "mma.sync.aligned.m16n8k16.row.col.f16.f16.f16.f16 "                  \
        "{%0,%1}, {%2,%3,%4,%5}, {%6,%7}, {%0,%1};"                           \
        : "+r"((cc)[0]), "+r"((cc)[1])                                        \
        : "r"((a)[0]), "r"((a)[1]), "r"((a)[2]), "r"((a)[3]),                 \
          "r"(b0), "r"(b1))

// ---------------- K0: transpose z[B,C,HW] -> g_xt / g_xh ----------------
__global__ void k_transpose(const float* __restrict__ z) {
    __shared__ float t[32][33];
    int b = blockIdx.z, c0 = blockIdx.y * 32, hw0 = blockIdx.x * 32;
    int tx = threadIdx.x, ty = threadIdx.y;        // (32, 8)
    #pragma unroll
    for (int i = ty; i < 32; i += 8)
        t[i][tx] = z[((size_t)(b * CDIM + c0 + i)) * HW + hw0 + tx];
    __syncthreads();
    #pragma unroll
    for (int i = ty; i < 32; i += 8) {
        float v = t[tx][i];
        size_t o = ((size_t)(b * HW + hw0 + i)) * CDIM + c0 + tx;
        g_xt[o] = v;
        g_xh[o] = __float2half(v);
    }
}

// ---------------- K0b: emb -> fp16 ----------------
__global__ void k_ehf(const float* __restrict__ emb) {
    int i = blockIdx.x * 256 + threadIdx.x;        // over KEMB*CDIM/4
    float4 v = reinterpret_cast<const float4*>(emb)[i];
    __half* o = g_eh + (size_t)i * 4;
    o[0] = __float2half(v.x); o[1] = __float2half(v.y);
    o[2] = __float2half(v.z); o[3] = __float2half(v.w);
}

// ---------------- K1: |x|^2 per row ----------------
__global__ void k_rownorm() {
    int row  = blockIdx.x * 8 + threadIdx.y;       // (32, 8)
    int lane = threadIdx.x;
    const float* r = g_xt + (size_t)row * CDIM;
    double acc = 0.0;
    #pragma unroll
    for (int h = 0; h < 2; h++) {
        float4 v = *reinterpret_cast<const float4*>(&r[h * 128 + lane * 4]);
        acc += (double)__fmul_rn(v.x, v.x);
        acc += (double)__fmul_rn(v.y, v.y);
        acc += (double)__fmul_rn(v.z, v.z);
        acc += (double)__fmul_rn(v.w, v.w);
    }
    #pragma unroll
    for (int off = 16; off > 0; off >>= 1)
        acc += __shfl_down_sync(0xffffffffu, acc, off);
    if (lane == 0) g_rownorm[row] = (float)acc;
}

// ---------------- K2: coarse fp16 mma.sync GEMM + per-tile top-4 ----------------
// (Round-11 champion GEMM, unchanged.)
__global__ __launch_bounds__(512, 2) void k_gemm_coarse() {
    extern __shared__ __align__(16) char smem[];
    const uint32_t sbase = smem_u32(smem);
    const int tid = threadIdx.x;
    const int rowBase = blockIdx.x * 128;
    const int colBase = blockIdx.y * 128;

    const char* Ag = (const char*)(g_xh + (size_t)rowBase * CDIM);
    const char* Bg = (const char*)(g_eh + (size_t)colBase * CDIM);

    const int ldr = tid >> 3, ldc = tid & 7;

    auto load_chunk = [&](int ch) {
        const uint32_t dA = sbase + (uint32_t)((ch & 1) * STAGE);
        const uint32_t dB = dA + ABUF;
        #pragma unroll
        for (int it = 0; it < 2; it++) {
            int r = ldr + it * 64;
            uint32_t so = (uint32_t)(r * APITCH + ldc * 16);
            size_t  go = ((size_t)r * CDIM + ch * 64 + ldc * 8) * 2;
            CP16(dA + so, Ag + go);
            CP16(dB + so, Bg + go);
        }
        CP_COMMIT();
    };

    const int lane = tid & 31, wid = tid >> 5;
    const int g = lane >> 2, m4 = lane & 3;
    const int mw = wid >> 2, nw = wid & 3;

    uint32_t c[2][4][2];
    #pragma unroll
    for (int mt = 0; mt < 2; mt++)
        #pragma unroll
        for (int nt = 0; nt < 4; nt++) { c[mt][nt][0] = 0u; c[mt][nt][1] = 0u; }

    const uint32_t aoff = (uint32_t)((mw * 32 + (lane & 15)) * APITCH
                                     + ((lane >> 4) & 1) * 16);
    const uint32_t boff = (uint32_t)(ABUF
                                     + (nw * 32 + ((lane >> 4) & 1) * 8 + (lane & 7)) * APITCH
                                     + ((lane >> 3) & 1) * 16);

    auto compute_chunk = [&](int ch) {
        const uint32_t sg = sbase + (uint32_t)((ch & 1) * STAGE);
        const uint32_t bA = sg + aoff;
        const uint32_t bB = sg + boff;
        #pragma unroll
        for (int ks = 0; ks < 4; ks++) {
            const uint32_t ko = ks * 32;
            uint32_t a[2][4], b[2][4];
            ldsm_x4(a[0][0], a[0][1], a[0][2], a[0][3], bA + ko);
            ldsm_x4(a[1][0], a[1][1], a[1][2], a[1][3], bA + 16 * APITCH + ko);
            ldsm_x4(b[0][0], b[0][1], b[0][2], b[0][3], bB + ko);
            ldsm_x4(b[1][0], b[1][1], b[1][2], b[1][3], bB + 16 * APITCH + ko);
            #pragma unroll
            for (int mt = 0; mt < 2; mt++)
                #pragma unroll
                for (int ntp = 0; ntp < 2; ntp++) {
                    MMA_F16(c[mt][ntp * 2],     a[mt], b[ntp][0], b[ntp][1]);
                    MMA_F16(c[mt][ntp * 2 + 1], a[mt], b[ntp][2], b[ntp][3]);
                }
        }
    };

    load_chunk(0);
    load_chunk(1);
    asm volatile("cp.async.wait_group 1;" ::: "memory");
    __syncthreads();
    compute_chunk(0);
    __syncthreads();
    load_chunk(2);
    asm volatile("cp.async.wait_group 1;" ::: "memory");
    __syncthreads();
    compute_chunk(1);
    __syncthreads();
    load_chunk(3);
    asm volatile("cp.async.wait_group 1;" ::: "memory");
    __syncthreads();
    compute_chunk(2);
    __syncthreads();
    asm volatile("cp.async.wait_group 0;" ::: "memory");
    __syncthreads();
    compute_chunk(3);
    __syncthreads();   // buffers dead; reuse smem for reduction

    float* redv = reinterpret_cast<float*>(smem);
    int*   redi = reinterpret_cast<int*>(smem) + 128 * RPW;

    #pragma unroll
    for (int lr = 0; lr < 4; lr++) {
        const int mt = lr >> 1, hf = lr & 1;
        float v0 = 1e30f, v1 = 1e30f, v2 = 1e30f, v3 = 1e30f;
        int   i0 = 0,     i1 = 0,     i2 = 0,     i3 = 0;
        #pragma unroll
        for (int nt = 0; nt < 4; nt++) {
            float2 f = __half22float2(*reinterpret_cast<__half2*>(&c[mt][nt][hf]));
            int j0 = colBase + nw * 32 + nt * 8 + m4 * 2;
            float dv0 = -2.0f * f.x;
            float dv1 = -2.0f * f.y;
            TOP4_INSERT(dv0, j0);
            TOP4_INSERT(dv1, j0 + 1);
        }
        #pragma unroll
        for (int s = 1; s <= 2; s <<= 1) {
            float w0 = __shfl_xor_sync(0xffffffffu, v0, s);
            float w1 = __shfl_xor_sync(0xffffffffu, v1, s);
            float w2 = __shfl_xor_sync(0xffffffffu, v2, s);
            float w3 = __shfl_xor_sync(0xffffffffu, v3, s);
            int   q0 = __shfl_xor_sync(0xffffffffu, i0, s);
            int   q1 = __shfl_xor_sync(0xffffffffu, i1, s);
            int   q2 = __shfl_xor_sync(0xffffffffu, i2, s);
            int   q3 = __shfl_xor_sync(0xffffffffu, i3, s);
            TOP4_INSERT(w0, q0); TOP4_INSERT(w1, q1);
            TOP4_INSERT(w2, q2); TOP4_INSERT(w3, q3);
        }
        if (m4 == 0) {
            int row = mw * 32 + mt * 16 + hf * 8 + g;
            int base = row * RPW + nw * 4;
            redv[base + 0] = v0; redv[base + 1] = v1;
            redv[base + 2] = v2; redv[base + 3] = v3;
            redi[base + 0] = i0; redi[base + 1] = i1;
            redi[base + 2] = i2; redi[base + 3] = i3;
        }
    }
    __syncthreads();

    if (tid < 128) {
        float v0 = 1e30f, v1 = 1e30f, v2 = 1e30f, v3 = 1e30f;
        int   i0 = 0,     i1 = 0,     i2 = 0,     i3 = 0;
        #pragma unroll
        for (int e = 0; e < 16; e++) {
            float dv = redv[tid * RPW + e];
            int j = redi[tid * RPW + e];
            TOP4_INSERT(dv, j);
        }
        int n = rowBase + tid;
        g_tv[(size_t)n * NTILES + blockIdx.y] = make_float4(v0, v1, v2, v3);
        g_ti[(size_t)n * NTILES + blockIdx.y] = make_int4(i0, i1, i2, i3);
    }
}

// ---------------- K3: exact rescore, warp-cooperative dots ----------------
// One warp per row; 256 stored entries; all entries within MARGIN of coarse min
// rescored with an fp32 dot whose error (~1e-9) is far below the fl32 grid of
// the comparator (ulp(256)/2 = 1.5e-5) -> identical buckets as the validated
// sequential chain. Lexicographic (d, j) min == first-index tie-break.
__global__ __launch_bounds__(128) void k_rescore(const float* __restrict__ emb,
                                                 float* __restrict__ idx_out_f) {
    const unsigned FULL = 0xffffffffu;
    int wid = threadIdx.x >> 5, lid = threadIdx.x & 31;
    int n = blockIdx.x * 4 + wid;
    const float4* tv = g_tv + (size_t)n * NTILES;
    const int4*   ti = g_ti + (size_t)n * NTILES;

    // x row resident in registers: lane owns elements [lid*8, lid*8+8)
    const float* xr = g_xt + (size_t)n * CDIM;
    float4 x0 = *reinterpret_cast<const float4*>(&xr[lid * 8]);
    float4 x1 = *reinterpret_cast<const float4*>(&xr[lid * 8 + 4]);
    const float S = g_rownorm[n];

    float ev[8]; int ei[8];
    #pragma unroll
    for (int q = 0; q < 8; q++) {
        int e = q * 32 + lid;                      // entry 0..255
        float4 v4 = tv[e >> 2];
        int4   i4 = ti[e >> 2];
        int rk = e & 3;
        ev[q] = (rk == 0) ? v4.x : (rk == 1) ? v4.y : (rk == 2) ? v4.z : v4.w;
        ei[q] = (rk == 0) ? i4.x : (rk == 1) ? i4.y : (rk == 2) ? i4.z : i4.w;
    }
    float m = 1e30f;
    #pragma unroll
    for (int q = 0; q < 8; q++) m = fminf(m, ev[q]);
    #pragma unroll
    for (int off = 16; off > 0; off >>= 1)
        m = fminf(m, __shfl_xor_sync(FULL, m, off));
    const float thr = m + MARGIN;

    float best = 1e30f; int bj = 0x7fffffff;
    #pragma unroll
    for (int q = 0; q < 8; q++) {
        unsigned mask = __ballot_sync(FULL, ev[q] <= thr);
        while (mask) {
            int src = __ffs(mask) - 1;
            mask &= mask - 1;
            int j = __shfl_sync(FULL, ei[q], src);
            const float* er = emb + (size_t)j * CDIM;
            float4 e0 = *reinterpret_cast<const float4*>(&er[lid * 8]);
            float4 e1 = *reinterpret_cast<const float4*>(&er[lid * 8 + 4]);
            float dot = 0.0f;
            dot = __fmaf_rn(x0.x, e0.x, dot);
            dot = __fmaf_rn(x0.y, e0.y, dot);
            dot = __fmaf_rn(x0.z, e0.z, dot);
            dot = __fmaf_rn(x0.w, e0.w, dot);
            dot = __fmaf_rn(x1.x, e1.x, dot);
            dot = __fmaf_rn(x1.y, e1.y, dot);
            dot = __fmaf_rn(x1.z, e1.z, dot);
            dot = __fmaf_rn(x1.w, e1.w, dot);
            #pragma unroll
            for (int off = 16; off > 0; off >>= 1)
                dot = __fadd_rn(dot, __shfl_xor_sync(FULL, dot, off));
            float d = __fadd_rn(S, -__fmul_rn(2.0f, dot));
            if (d < best || (d == best && j < bj)) { best = d; bj = j; }
        }
    }
    if (lid == 0) {
        g_idx[n] = bj;
        idx_out_f[n] = (float)bj;
    }
}

// ---------------- K4: transpose-free output + loss partials ----------------
// out[b][c][hw] = fl(z + fl(q - z)), reading original z (coalesced along hw),
// gathering emb rows via L1 (idx4 reused across 8 c-iterations).
__global__ __launch_bounds__(256) void k_output(const float* __restrict__ z,
                                                const float* __restrict__ emb,
                                                float* __restrict__ out) {
    __shared__ double sred[8];
    int b = blockIdx.z, c0 = blockIdx.y * 32, hw0 = blockIdx.x * 256;
    int tx = threadIdx.x, ty = threadIdx.y;        // (64, 4)
    int hw = hw0 + tx * 4;
    int n0 = b * HW + hw;
    int4 id4 = *reinterpret_cast<const int4*>(&g_idx[n0]);

    double acc = 0.0;
    #pragma unroll
    for (int i = 0; i < 8; i++) {
        int c = c0 + ty + i * 4;
        size_t zoff = ((size_t)(b * CDIM + c)) * HW + hw;
        float4 zv = *reinterpret_cast<const float4*>(&z[zoff]);
        float q0 = emb[(size_t)id4.x * CDIM + c];
        float q1 = emb[(size_t)id4.y * CDIM + c];
        float q2 = emb[(size_t)id4.z * CDIM + c];
        float q3 = emb[(size_t)id4.w * CDIM + c];
        float t0 = __fsub_rn(q0, zv.x);
        float t1 = __fsub_rn(q1, zv.y);
        float t2 = __fsub_rn(q2, zv.z);
        float t3 = __fsub_rn(q3, zv.w);
        float4 o;
        o.x = __fadd_rn(zv.x, t0);
        o.y = __fadd_rn(zv.y, t1);
        o.z = __fadd_rn(zv.z, t2);
        o.w = __fadd_rn(zv.w, t3);
        *reinterpret_cast<float4*>(&out[zoff]) = o;
        acc += (double)__fmul_rn(t0, t0);
        acc += (double)__fmul_rn(t1, t1);
        acc += (double)__fmul_rn(t2, t2);
        acc += (double)__fmul_rn(t3, t3);
    }

    int tid = ty * 64 + tx;
    #pragma unroll
    for (int off = 16; off > 0; off >>= 1)
        acc += __shfl_down_sync(0xffffffffu, acc, off);
    if ((tid & 31) == 0) sred[tid >> 5] = acc;
    __syncthreads();
    if (tid == 0) {
        double s = 0.0;
        #pragma unroll
        for (int w = 0; w < 8; w++) s += sred[w];
        g_partial[blockIdx.x + 4 * (blockIdx.y + 8 * blockIdx.z)] = s;
    }
}

// ---------------- K5: final loss reduce ----------------
__global__ void k_loss(float* __restrict__ out_loss) {
    __shared__ double sred[256];
    int tid = threadIdx.x;
    double acc = 0.0;
    for (int q = tid; q < 512; q += 256) acc += g_partial[q];
    sred[tid] = acc;
    __syncthreads();
    for (int s = 128; s > 0; s >>= 1) {
        if (tid < s) sred[tid] += sred[tid + s];
        __syncthreads();
    }
    if (tid == 0) {
        float m = (float)(sred[0] / (double)OUT_N);
        out_loss[0] = __fadd_rn(m, __fmul_rn(0.25f, m));
    }
}

// ---------------- entry ----------------
extern "C" void kernel_launch(void* const* d_in, const int* in_sizes, int n_in,
                              void* d_out, int out_size) {
    const float* z   = (const float*)d_in[0];
    const float* emb = (const float*)d_in[1];
    float* out    = (float*)d_out;
    float* loss_p = out + OUT_N;
    float* idx_p  = out + OUT_N + 1;

    cudaFuncSetAttribute(k_gemm_coarse,
                         cudaFuncAttributeMaxDynamicSharedMemorySize, GEMM_SMEM);

    k_transpose<<<dim3(32, 8, 16), dim3(32, 8)>>>(z);
    k_ehf<<<(KEMB * CDIM / 4) / 256, 256>>>(emb);
    k_rownorm<<<NROWS / 8, dim3(32, 8)>>>();
    k_gemm_coarse<<<dim3(NROWS / 128, KEMB / 128), 512, GEMM_SMEM>>>();
    k_rescore<<<NROWS / 4, 128>>>(emb, idx_p);
    k_output<<<dim3(4, 8, 16), dim3(64, 4)>>>(z, emb, out);
    k_loss<<<1, 256>>>(loss_p);
}

// round 13
// speedup vs baseline: 2.2593x; 1.3545x over previous
#include <cuda_runtime.h>
#include <cuda_fp16.h>
#include <cstdint>

#define NROWS 16384
#define CDIM  256
#define KEMB  8192
#define NBATCH 16
#define HW    1024
#define OUT_N (NBATCH * CDIM * HW)   // 4194304

#define NTILES 64                     // 8192 / 128 column tiles
#define MARGIN 6.0e-4f

#define APITCH 144                    // smem row pitch (bytes): 64 fp16 + 16B pad
#define ABUF   (128 * APITCH)
#define BBUF   (128 * APITCH)
#define STAGE  (ABUF + BBUF)          // 36864 B
#define GEMM_SMEM (2 * STAGE)         // 73728 B -> 2 CTAs/SM

// ---------------- static device scratch ----------------
__device__ float   g_xt[NROWS * CDIM];    // z transposed [n][c] fp32
__device__ __half  g_xh[NROWS * CDIM];    // fp16(x)
__device__ __half  g_eh[KEMB * CDIM];     // fp16(emb)
__device__ float   g_rownorm[NROWS];
__device__ int     g_idx[NROWS];
__device__ double  g_partial[512];
__device__ float4  g_tv[NROWS * NTILES];  // candidate dv slots per (row,tile)
__device__ int4    g_ti[NROWS * NTILES];  // matching indices

__device__ __forceinline__ uint32_t smem_u32(const void* p) {
    uint32_t a;
    asm("{ .reg .u64 t; cvta.to.shared.u64 t, %1; cvt.u32.u64 %0, t; }" : "=r"(a) : "l"(p));
    return a;
}
__device__ __forceinline__ void ldsm_x4(uint32_t& r0, uint32_t& r1, uint32_t& r2,
                                        uint32_t& r3, uint32_t addr) {
    asm volatile("ldmatrix.sync.aligned.m8n8.x4.shared.b16 {%0,%1,%2,%3}, [%4];"
                 : "=r"(r0), "=r"(r1), "=r"(r2), "=r"(r3) : "r"(addr));
}
#define CP16(dst, src) \
    asm volatile("cp.async.cg.shared.global [%0], [%1], 16;" :: "r"(dst), "l"(src))
#define CP_COMMIT() asm volatile("cp.async.commit_group;" ::: "memory")

// fp16-accumulate MMA: D/C are 2x b32 regs (4 halves)
#define MMA_F16(cc, a, b0, b1)                                                \
    asm volatile(                                                             \
        "mma.sync.aligned.m16n8k16.row.col.f16.f16.f16.f16 "                  \
        "{%0,%1}, {%2,%3,%4,%5}, {%6,%7}, {%0,%1};"                           \
        : "+r"((cc)[0]), "+r"((cc)[1])                                        \
        : "r"((a)[0]), "r"((a)[1]), "r"((a)[2]), "r"((a)[3]),                 \
          "r"(b0), "r"(b1))

// ---------------- K0: transpose z[B,C,HW] -> g_xt / g_xh ----------------
__global__ void k_transpose(const float* __restrict__ z) {
    __shared__ float t[32][33];
    int b = blockIdx.z, c0 = blockIdx.y * 32, hw0 = blockIdx.x * 32;
    int tx = threadIdx.x, ty = threadIdx.y;        // (32, 8)
    #pragma unroll
    for (int i = ty; i < 32; i += 8)
        t[i][tx] = z[((size_t)(b * CDIM + c0 + i)) * HW + hw0 + tx];
    __syncthreads();
    #pragma unroll
    for (int i = ty; i < 32; i += 8) {
        float v = t[tx][i];
        size_t o = ((size_t)(b * HW + hw0 + i)) * CDIM + c0 + tx;
        g_xt[o] = v;
        g_xh[o] = __float2half(v);
    }
}

// ---------------- K0b: emb -> fp16 ----------------
__global__ void k_ehf(const float* __restrict__ emb) {
    int i = blockIdx.x * 256 + threadIdx.x;        // over KEMB*CDIM/4
    float4 v = reinterpret_cast<const float4*>(emb)[i];
    __half* o = g_eh + (size_t)i * 4;
    o[0] = __float2half(v.x); o[1] = __float2half(v.y);
    o[2] = __float2half(v.z); o[3] = __float2half(v.w);
}

// ---------------- K1: |x|^2 per row ----------------
__global__ void k_rownorm() {
    int row  = blockIdx.x * 8 + threadIdx.y;       // (32, 8)
    int lane = threadIdx.x;
    const float* r = g_xt + (size_t)row * CDIM;
    double acc = 0.0;
    #pragma unroll
    for (int h = 0; h < 2; h++) {
        float4 v = *reinterpret_cast<const float4*>(&r[h * 128 + lane * 4]);
        acc += (double)__fmul_rn(v.x, v.x);
        acc += (double)__fmul_rn(v.y, v.y);
        acc += (double)__fmul_rn(v.z, v.z);
        acc += (double)__fmul_rn(v.w, v.w);
    }
    #pragma unroll
    for (int off = 16; off > 0; off >>= 1)
        acc += __shfl_down_sync(0xffffffffu, acc, off);
    if (lane == 0) g_rownorm[row] = (float)acc;
}

// ---------------- K2: coarse fp16 mma.sync GEMM + threshold-collect ----------
// Mainloop identical to R12 champion. Epilogue: per-row min via hmax2 trees +
// margin-threshold candidate collection into 4 slots (set-deterministic).
__global__ __launch_bounds__(512, 2) void k_gemm_coarse() {
    extern __shared__ __align__(16) char smem[];
    const uint32_t sbase = smem_u32(smem);
    const int tid = threadIdx.x;
    const int rowBase = blockIdx.x * 128;
    const int colBase = blockIdx.y * 128;
    const unsigned FULL = 0xffffffffu;

    const char* Ag = (const char*)(g_xh + (size_t)rowBase * CDIM);
    const char* Bg = (const char*)(g_eh + (size_t)colBase * CDIM);

    const int ldr = tid >> 3, ldc = tid & 7;

    auto load_chunk = [&](int ch) {
        const uint32_t dA = sbase + (uint32_t)((ch & 1) * STAGE);
        const uint32_t dB = dA + ABUF;
        #pragma unroll
        for (int it = 0; it < 2; it++) {
            int r = ldr + it * 64;
            uint32_t so = (uint32_t)(r * APITCH + ldc * 16);
            size_t  go = ((size_t)r * CDIM + ch * 64 + ldc * 8) * 2;
            CP16(dA + so, Ag + go);
            CP16(dB + so, Bg + go);
        }
        CP_COMMIT();
    };

    const int lane = tid & 31, wid = tid >> 5;
    const int g = lane >> 2, m4 = lane & 3;
    const int mw = wid >> 2, nw = wid & 3;

    uint32_t c[2][4][2];
    #pragma unroll
    for (int mt = 0; mt < 2; mt++)
        #pragma unroll
        for (int nt = 0; nt < 4; nt++) { c[mt][nt][0] = 0u; c[mt][nt][1] = 0u; }

    const uint32_t aoff = (uint32_t)((mw * 32 + (lane & 15)) * APITCH
                                     + ((lane >> 4) & 1) * 16);
    const uint32_t boff = (uint32_t)(ABUF
                                     + (nw * 32 + ((lane >> 4) & 1) * 8 + (lane & 7)) * APITCH
                                     + ((lane >> 3) & 1) * 16);

    auto compute_chunk = [&](int ch) {
        const uint32_t sg = sbase + (uint32_t)((ch & 1) * STAGE);
        const uint32_t bA = sg + aoff;
        const uint32_t bB = sg + boff;
        #pragma unroll
        for (int ks = 0; ks < 4; ks++) {
            const uint32_t ko = ks * 32;
            uint32_t a[2][4], b[2][4];
            ldsm_x4(a[0][0], a[0][1], a[0][2], a[0][3], bA + ko);
            ldsm_x4(a[1][0], a[1][1], a[1][2], a[1][3], bA + 16 * APITCH + ko);
            ldsm_x4(b[0][0], b[0][1], b[0][2], b[0][3], bB + ko);
            ldsm_x4(b[1][0], b[1][1], b[1][2], b[1][3], bB + 16 * APITCH + ko);
            #pragma unroll
            for (int mt = 0; mt < 2; mt++)
                #pragma unroll
                for (int ntp = 0; ntp < 2; ntp++) {
                    MMA_F16(c[mt][ntp * 2],     a[mt], b[ntp][0], b[ntp][1]);
                    MMA_F16(c[mt][ntp * 2 + 1], a[mt], b[ntp][2], b[ntp][3]);
                }
        }
    };

    load_chunk(0);
    load_chunk(1);
    asm volatile("cp.async.wait_group 1;" ::: "memory");
    __syncthreads();
    compute_chunk(0);
    __syncthreads();
    load_chunk(2);
    asm volatile("cp.async.wait_group 1;" ::: "memory");
    __syncthreads();
    compute_chunk(1);
    __syncthreads();
    load_chunk(3);
    asm volatile("cp.async.wait_group 1;" ::: "memory");
    __syncthreads();
    compute_chunk(2);
    __syncthreads();
    asm volatile("cp.async.wait_group 0;" ::: "memory");
    __syncthreads();
    compute_chunk(3);
    __syncthreads();   // buffers dead; reuse smem for reduction

    // epilogue smem (all within dead stage-0 region)
    float* sv   = reinterpret_cast<float*>(smem);            // [128][4] slot dv
    int*   si   = reinterpret_cast<int*>(smem) + 512;        // [128][4] slot idx
    float* srm  = reinterpret_cast<float*>(smem) + 1024;     // [128][4] per-nw rowmin
    float* sthr = reinterpret_cast<float*>(smem) + 1536;     // [128] row threshold
    int*   scnt = reinterpret_cast<int*>(smem)  + 1664;      // [128] slot counters

    // ---- Phase A: per-row max-dot (== min dv) via hmax2 trees ----
    __half hmx[4];
    #pragma unroll
    for (int lr = 0; lr < 4; lr++) {
        const int mt = lr >> 1, hf = lr & 1;
        __half2 m01 = __hmax2(*reinterpret_cast<__half2*>(&c[mt][0][hf]),
                              *reinterpret_cast<__half2*>(&c[mt][1][hf]));
        __half2 m23 = __hmax2(*reinterpret_cast<__half2*>(&c[mt][2][hf]),
                              *reinterpret_cast<__half2*>(&c[mt][3][hf]));
        __half2 m = __hmax2(m01, m23);
        __half hm = __hmax(__low2half(m), __high2half(m));
        hmx[lr] = hm;
        float dv = __fmul_rn(-2.0f, __half2float(hm));
        dv = fminf(dv, __shfl_xor_sync(FULL, dv, 1));
        dv = fminf(dv, __shfl_xor_sync(FULL, dv, 2));
        if (m4 == 0) {
            int row = mw * 32 + mt * 16 + hf * 8 + g;
            srm[row * 4 + nw] = dv;
        }
    }
    __syncthreads();
    if (tid < 128) {
        float r0 = srm[tid * 4], r1 = srm[tid * 4 + 1];
        float r2 = srm[tid * 4 + 2], r3 = srm[tid * 4 + 3];
        sthr[tid] = fminf(fminf(r0, r1), fminf(r2, r3)) + MARGIN;
        scnt[tid] = 0;
        sv[tid * 4 + 0] = 1e30f; sv[tid * 4 + 1] = 1e30f;
        sv[tid * 4 + 2] = 1e30f; sv[tid * 4 + 3] = 1e30f;
        si[tid * 4 + 0] = 0; si[tid * 4 + 1] = 0;
        si[tid * 4 + 2] = 0; si[tid * 4 + 3] = 0;
    }
    __syncthreads();

    // ---- Phase B: threshold collect (fast path skips whole row-part) ----
    #pragma unroll
    for (int lr = 0; lr < 4; lr++) {
        const int mt = lr >> 1, hf = lr & 1;
        int row = mw * 32 + mt * 16 + hf * 8 + g;
        float thr = sthr[row];
        // dv <= thr  <=>  h >= -thr/2 ; round-down keeps capture a superset
        __half T = __float2half_rd(__fmul_rn(-0.5f, thr));
        if (__hge(hmx[lr], T)) {
            #pragma unroll
            for (int nt = 0; nt < 4; nt++) {
                float2 f = __half22float2(*reinterpret_cast<__half2*>(&c[mt][nt][hf]));
                int j0 = colBase + nw * 32 + nt * 8 + m4 * 2;
                float dv0 = __fmul_rn(-2.0f, f.x);
                float dv1 = __fmul_rn(-2.0f, f.y);
                if (dv0 <= thr) {
                    int s = atomicAdd(&scnt[row], 1);
                    if (s < 4) { sv[row * 4 + s] = dv0; si[row * 4 + s] = j0; }
                }
                if (dv1 <= thr) {
                    int s = atomicAdd(&scnt[row], 1);
                    if (s < 4) { sv[row * 4 + s] = dv1; si[row * 4 + s] = j0 + 1; }
                }
            }
        }
    }
    __syncthreads();

    if (tid < 128) {
        int n = rowBase + tid;
        g_tv[(size_t)n * NTILES + blockIdx.y] =
            make_float4(sv[tid * 4], sv[tid * 4 + 1], sv[tid * 4 + 2], sv[tid * 4 + 3]);
        g_ti[(size_t)n * NTILES + blockIdx.y] =
            make_int4(si[tid * 4], si[tid * 4 + 1], si[tid * 4 + 2], si[tid * 4 + 3]);
    }
}

// ---------------- K3: exact rescore, warp-cooperative dots ----------------
// Order-independent over stored candidate SETS: threshold vs global coarse min,
// exact fp32 dot (error ~1e-9 << comparator grid), lexicographic (d, j) min.
__global__ __launch_bounds__(128) void k_rescore(const float* __restrict__ emb,
                                                 float* __restrict__ idx_out_f) {
    const unsigned FULL = 0xffffffffu;
    int wid = threadIdx.x >> 5, lid = threadIdx.x & 31;
    int n = blockIdx.x * 4 + wid;
    const float4* tv = g_tv + (size_t)n * NTILES;
    const int4*   ti = g_ti + (size_t)n * NTILES;

    const float* xr = g_xt + (size_t)n * CDIM;
    float4 x0 = *reinterpret_cast<const float4*>(&xr[lid * 8]);
    float4 x1 = *reinterpret_cast<const float4*>(&xr[lid * 8 + 4]);
    const float S = g_rownorm[n];

    float ev[8]; int ei[8];
    #pragma unroll
    for (int q = 0; q < 8; q++) {
        int e = q * 32 + lid;                      // entry 0..255
        float4 v4 = tv[e >> 2];
        int4   i4 = ti[e >> 2];
        int rk = e & 3;
        ev[q] = (rk == 0) ? v4.x : (rk == 1) ? v4.y : (rk == 2) ? v4.z : v4.w;
        ei[q] = (rk == 0) ? i4.x : (rk == 1) ? i4.y : (rk == 2) ? i4.z : i4.w;
    }
    float m = 1e30f;
    #pragma unroll
    for (int q = 0; q < 8; q++) m = fminf(m, ev[q]);
    #pragma unroll
    for (int off = 16; off > 0; off >>= 1)
        m = fminf(m, __shfl_xor_sync(FULL, m, off));
    const float thr = m + MARGIN;

    float best = 1e30f; int bj = 0x7fffffff;
    #pragma unroll
    for (int q = 0; q < 8; q++) {
        unsigned mask = __ballot_sync(FULL, ev[q] <= thr);
        while (mask) {
            int src = __ffs(mask) - 1;
            mask &= mask - 1;
            int j = __shfl_sync(FULL, ei[q], src);
            const float* er = emb + (size_t)j * CDIM;
            float4 e0 = *reinterpret_cast<const float4*>(&er[lid * 8]);
            float4 e1 = *reinterpret_cast<const float4*>(&er[lid * 8 + 4]);
            float dot = 0.0f;
            dot = __fmaf_rn(x0.x, e0.x, dot);
            dot = __fmaf_rn(x0.y, e0.y, dot);
            dot = __fmaf_rn(x0.z, e0.z, dot);
            dot = __fmaf_rn(x0.w, e0.w, dot);
            dot = __fmaf_rn(x1.x, e1.x, dot);
            dot = __fmaf_rn(x1.y, e1.y, dot);
            dot = __fmaf_rn(x1.z, e1.z, dot);
            dot = __fmaf_rn(x1.w, e1.w, dot);
            #pragma unroll
            for (int off = 16; off > 0; off >>= 1)
                dot = __fadd_rn(dot, __shfl_xor_sync(FULL, dot, off));
            float d = __fadd_rn(S, -__fmul_rn(2.0f, dot));
            if (d < best || (d == best && j < bj)) { best = d; bj = j; }
        }
    }
    if (lid == 0) {
        g_idx[n] = bj;
        idx_out_f[n] = (float)bj;
    }
}

// ---------------- K4: transpose-free output + loss partials ----------------
__global__ __launch_bounds__(256) void k_output(const float* __restrict__ z,
                                                const float* __restrict__ emb,
                                                float* __restrict__ out) {
    __shared__ double sred[8];
    int b = blockIdx.z, c0 = blockIdx.y * 32, hw0 = blockIdx.x * 256;
    int tx = threadIdx.x, ty = threadIdx.y;        // (64, 4)
    int hw = hw0 + tx * 4;
    int n0 = b * HW + hw;
    int4 id4 = *reinterpret_cast<const int4*>(&g_idx[n0]);

    double acc = 0.0;
    #pragma unroll
    for (int i = 0; i < 8; i++) {
        int c = c0 + ty + i * 4;
        size_t zoff = ((size_t)(b * CDIM + c)) * HW + hw;
        float4 zv = *reinterpret_cast<const float4*>(&z[zoff]);
        float q0 = emb[(size_t)id4.x * CDIM + c];
        float q1 = emb[(size_t)id4.y * CDIM + c];
        float q2 = emb[(size_t)id4.z * CDIM + c];
        float q3 = emb[(size_t)id4.w * CDIM + c];
        float t0 = __fsub_rn(q0, zv.x);
        float t1 = __fsub_rn(q1, zv.y);
        float t2 = __fsub_rn(q2, zv.z);
        float t3 = __fsub_rn(q3, zv.w);
        float4 o;
        o.x = __fadd_rn(zv.x, t0);
        o.y = __fadd_rn(zv.y, t1);
        o.z = __fadd_rn(zv.z, t2);
        o.w = __fadd_rn(zv.w, t3);
        *reinterpret_cast<float4*>(&out[zoff]) = o;
        acc += (double)__fmul_rn(t0, t0);
        acc += (double)__fmul_rn(t1, t1);
        acc += (double)__fmul_rn(t2, t2);
        acc += (double)__fmul_rn(t3, t3);
    }

    int tid = ty * 64 + tx;
    #pragma unroll
    for (int off = 16; off > 0; off >>= 1)
        acc += __shfl_down_sync(0xffffffffu, acc, off);
    if ((tid & 31) == 0) sred[tid >> 5] = acc;
    __syncthreads();
    if (tid == 0) {
        double s = 0.0;
        #pragma unroll
        for (int w = 0; w < 8; w++) s += sred[w];
        g_partial[blockIdx.x + 4 * (blockIdx.y + 8 * blockIdx.z)] = s;
    }
}

// ---------------- K5: final loss reduce ----------------
__global__ void k_loss(float* __restrict__ out_loss) {
    __shared__ double sred[256];
    int tid = threadIdx.x;
    double acc = 0.0;
    for (int q = tid; q < 512; q += 256) acc += g_partial[q];
    sred[tid] = acc;
    __syncthreads();
    for (int s = 128; s > 0; s >>= 1) {
        if (tid < s) sred[tid] += sred[tid + s];
        __syncthreads();
    }
    if (tid == 0) {
        float m = (float)(sred[0] / (double)OUT_N);
        out_loss[0] = __fadd_rn(m, __fmul_rn(0.25f, m));
    }
}

// ---------------- entry ----------------
extern "C" void kernel_launch(void* const* d_in, const int* in_sizes, int n_in,
                              void* d_out, int out_size) {
    const float* z   = (const float*)d_in[0];
    const float* emb = (const float*)d_in[1];
    float* out    = (float*)d_out;
    float* loss_p = out + OUT_N;
    float* idx_p  = out + OUT_N + 1;

    cudaFuncSetAttribute(k_gemm_coarse,
                         cudaFuncAttributeMaxDynamicSharedMemorySize, GEMM_SMEM);

    k_transpose<<<dim3(32, 8, 16), dim3(32, 8)>>>(z);
    k_ehf<<<(KEMB * CDIM / 4) / 256, 256>>>(emb);
    k_rownorm<<<NROWS / 8, dim3(32, 8)>>>();
    k_gemm_coarse<<<dim3(NROWS / 128, KEMB / 128), 512, GEMM_SMEM>>>();
    k_rescore<<<NROWS / 4, 128>>>(emb, idx_p);
    k_output<<<dim3(4, 8, 16), dim3(64, 4)>>>(z, emb, out);
    k_loss<<<1, 256>>>(loss_p);
}

// round 14
// speedup vs baseline: 2.4335x; 1.0771x over previous
#include <cuda_runtime.h>
#include <cuda_fp16.h>
#include <cstdint>

#define NROWS 16384
#define CDIM  256
#define KEMB  8192
#define NBATCH 16
#define HW    1024
#define OUT_N (NBATCH * CDIM * HW)   // 4194304

#define NTILES 64                     // 8192 / 128 column tiles
#define MARGIN 6.0e-4f

#define APITCH 144                    // smem row pitch (bytes): 64 fp16 + 16B pad
#define ABUF   (256 * APITCH)         // A chunk: 256 rows (36864 B)
#define BBUF   (128 * APITCH)         // B chunk: 128 codewords (18432 B)
#define STAGE  (ABUF + BBUF)          // 55296 B
#define GEMM_SMEM (2 * STAGE)         // 110592 B -> 2 CTAs/SM

// ---------------- static device scratch ----------------
__device__ float   g_xt[NROWS * CDIM];    // z transposed [n][c] fp32
__device__ __half  g_xh[NROWS * CDIM];    // fp16(x)
__device__ __half  g_eh[KEMB * CDIM];     // fp16(emb)
__device__ float   g_rownorm[NROWS];
__device__ int     g_idx[NROWS];
__device__ double  g_partial[512];
__device__ float4  g_tv[NROWS * NTILES];  // candidate dv slots per (row,tile)
__device__ int4    g_ti[NROWS * NTILES];  // matching indices

__device__ __forceinline__ uint32_t smem_u32(const void* p) {
    uint32_t a;
    asm("{ .reg .u64 t; cvta.to.shared.u64 t, %1; cvt.u32.u64 %0, t; }" : "=r"(a) : "l"(p));
    return a;
}
__device__ __forceinline__ void ldsm_x4(uint32_t& r0, uint32_t& r1, uint32_t& r2,
                                        uint32_t& r3, uint32_t addr) {
    asm volatile("ldmatrix.sync.aligned.m8n8.x4.shared.b16 {%0,%1,%2,%3}, [%4];"
                 : "=r"(r0), "=r"(r1), "=r"(r2), "=r"(r3) : "r"(addr));
}
#define CP16(dst, src) \
    asm volatile("cp.async.cg.shared.global [%0], [%1], 16;" :: "r"(dst), "l"(src))
#define CP_COMMIT() asm volatile("cp.async.commit_group;" ::: "memory")

// fp16-accumulate MMA: D/C are 2x b32 regs (4 halves)
#define MMA_F16(cc, a, b0, b1)                                                \
    asm volatile(                                                             \
        "mma.sync.aligned.m16n8k16.row.col.f16.f16.f16.f16 "                  \
        "{%0,%1}, {%2,%3,%4,%5}, {%6,%7}, {%0,%1};"                           \
        : "+r"((cc)[0]), "+r"((cc)[1])                                        \
        : "r"((a)[0]), "r"((a)[1]), "r"((a)[2]), "r"((a)[3]),                 \
          "r"(b0), "r"(b1))

// ---------------- K0: transpose z[B,C,HW] -> g_xt / g_xh ----------------
__global__ void k_transpose(const float* __restrict__ z) {
    __shared__ float t[32][33];
    int b = blockIdx.z, c0 = blockIdx.y * 32, hw0 = blockIdx.x * 32;
    int tx = threadIdx.x, ty = threadIdx.y;        // (32, 8)
    #pragma unroll
    for (int i = ty; i < 32; i += 8)
        t[i][tx] = z[((size_t)(b * CDIM + c0 + i)) * HW + hw0 + tx];
    __syncthreads();
    #pragma unroll
    for (int i = ty; i < 32; i += 8) {
        float v = t[tx][i];
        size_t o = ((size_t)(b * HW + hw0 + i)) * CDIM + c0 + tx;
        g_xt[o] = v;
        g_xh[o] = __float2half(v);
    }
}

// ---------------- K0b: emb -> fp16 ----------------
__global__ void k_ehf(const float* __restrict__ emb) {
    int i = blockIdx.x * 256 + threadIdx.x;        // over KEMB*CDIM/4
    float4 v = reinterpret_cast<const float4*>(emb)[i];
    __half* o = g_eh + (size_t)i * 4;
    o[0] = __float2half(v.x); o[1] = __float2half(v.y);
    o[2] = __float2half(v.z); o[3] = __float2half(v.w);
}

// ---------------- K1: |x|^2 per row ----------------
__global__ void k_rownorm() {
    int row  = blockIdx.x * 8 + threadIdx.y;       // (32, 8)
    int lane = threadIdx.x;
    const float* r = g_xt + (size_t)row * CDIM;
    double acc = 0.0;
    #pragma unroll
    for (int h = 0; h < 2; h++) {
        float4 v = *reinterpret_cast<const float4*>(&r[h * 128 + lane * 4]);
        acc += (double)__fmul_rn(v.x, v.x);
        acc += (double)__fmul_rn(v.y, v.y);
        acc += (double)__fmul_rn(v.z, v.z);
        acc += (double)__fmul_rn(v.w, v.w);
    }
    #pragma unroll
    for (int off = 16; off > 0; off >>= 1)
        acc += __shfl_down_sync(0xffffffffu, acc, off);
    if (lane == 0) g_rownorm[row] = (float)acc;
}

// ---------------- K2: coarse fp16 GEMM, 64x64 warp tiles + threshold-collect --
// CTA: 256 rows x 128 cols, 256 thr = 8 warps (4m x 2n), warp tile 64x64
// (1.0 crossbar wavefront per MMA). K=256 as 4 chunks of 64, 2-stage cp.async.
__global__ __launch_bounds__(256, 2) void k_gemm_coarse() {
    extern __shared__ __align__(16) char smem[];
    const uint32_t sbase = smem_u32(smem);
    const int tid = threadIdx.x;
    const int rowBase = blockIdx.x * 256;
    const int colBase = blockIdx.y * 128;
    const unsigned FULL = 0xffffffffu;

    const char* Ag = (const char*)(g_xh + (size_t)rowBase * CDIM);
    const char* Bg = (const char*)(g_eh + (size_t)colBase * CDIM);

    const int ldr = tid >> 3, ldc = tid & 7;       // r-group 0..31, granule 0..7

    auto load_chunk = [&](int ch) {
        const uint32_t dA = sbase + (uint32_t)((ch & 1) * STAGE);
        const uint32_t dB = dA + ABUF;
        #pragma unroll
        for (int it = 0; it < 8; it++) {           // A: 256 rows x 8 granules
            int r = ldr + it * 32;
            CP16(dA + (uint32_t)(r * APITCH + ldc * 16),
                 Ag + ((size_t)r * CDIM + ch * 64 + ldc * 8) * 2);
        }
        #pragma unroll
        for (int it = 0; it < 4; it++) {           // B: 128 rows x 8 granules
            int r = ldr + it * 32;
            CP16(dB + (uint32_t)(r * APITCH + ldc * 16),
                 Bg + ((size_t)r * CDIM + ch * 64 + ldc * 8) * 2);
        }
        CP_COMMIT();
    };

    const int lane = tid & 31, wid = tid >> 5;
    const int g = lane >> 2, m4 = lane & 3;
    const int mw = wid >> 1, nw = wid & 1;         // 4 m-groups x 2 n-groups

    uint32_t c[4][8][2];
    #pragma unroll
    for (int mt = 0; mt < 4; mt++)
        #pragma unroll
        for (int nt = 0; nt < 8; nt++) { c[mt][nt][0] = 0u; c[mt][nt][1] = 0u; }

    const uint32_t aoff = (uint32_t)((mw * 64 + (lane & 15)) * APITCH
                                     + ((lane >> 4) & 1) * 16);
    const uint32_t boff = (uint32_t)(ABUF
                                     + (nw * 64 + ((lane >> 4) & 1) * 8 + (lane & 7)) * APITCH
                                     + ((lane >> 3) & 1) * 16);

    auto compute_chunk = [&](int ch) {
        const uint32_t sg = sbase + (uint32_t)((ch & 1) * STAGE);
        const uint32_t bA = sg + aoff;
        const uint32_t bB = sg + boff;
        #pragma unroll
        for (int ks = 0; ks < 4; ks++) {
            const uint32_t ko = ks * 32;
            uint32_t a[4][4], b[4][4];
            #pragma unroll
            for (int mt = 0; mt < 4; mt++)
                ldsm_x4(a[mt][0], a[mt][1], a[mt][2], a[mt][3],
                        bA + mt * 16 * APITCH + ko);
            #pragma unroll
            for (int ntp = 0; ntp < 4; ntp++)
                ldsm_x4(b[ntp][0], b[ntp][1], b[ntp][2], b[ntp][3],
                        bB + ntp * 16 * APITCH + ko);
            #pragma unroll
            for (int mt = 0; mt < 4; mt++)
                #pragma unroll
                for (int ntp = 0; ntp < 4; ntp++) {
                    MMA_F16(c[mt][ntp * 2],     a[mt], b[ntp][0], b[ntp][1]);
                    MMA_F16(c[mt][ntp * 2 + 1], a[mt], b[ntp][2], b[ntp][3]);
                }
        }
    };

    load_chunk(0);
    load_chunk(1);
    asm volatile("cp.async.wait_group 1;" ::: "memory");
    __syncthreads();
    compute_chunk(0);
    __syncthreads();
    load_chunk(2);
    asm volatile("cp.async.wait_group 1;" ::: "memory");
    __syncthreads();
    compute_chunk(1);
    __syncthreads();
    load_chunk(3);
    asm volatile("cp.async.wait_group 1;" ::: "memory");
    __syncthreads();
    compute_chunk(2);
    __syncthreads();
    asm volatile("cp.async.wait_group 0;" ::: "memory");
    __syncthreads();
    compute_chunk(3);
    __syncthreads();   // buffers dead; reuse smem for reduction

    // epilogue smem (within dead stage-0 region)
    float* sv   = reinterpret_cast<float*>(smem);            // [256][4] slot dv
    int*   si   = reinterpret_cast<int*>(smem) + 1024;       // [256][4] slot idx
    float* srm  = reinterpret_cast<float*>(smem) + 2048;     // [256][2] per-nw rowmin
    float* sthr = reinterpret_cast<float*>(smem) + 2560;     // [256] row threshold
    int*   scnt = reinterpret_cast<int*>(smem)  + 2816;      // [256] slot counters

    // ---- Phase A: per-row max-dot (== min dv) via hmax2 trees ----
    __half hmx[8];
    #pragma unroll
    for (int lr = 0; lr < 8; lr++) {
        const int mt = lr >> 1, hf = lr & 1;
        __half2 m01 = __hmax2(*reinterpret_cast<__half2*>(&c[mt][0][hf]),
                              *reinterpret_cast<__half2*>(&c[mt][1][hf]));
        __half2 m23 = __hmax2(*reinterpret_cast<__half2*>(&c[mt][2][hf]),
                              *reinterpret_cast<__half2*>(&c[mt][3][hf]));
        __half2 m45 = __hmax2(*reinterpret_cast<__half2*>(&c[mt][4][hf]),
                              *reinterpret_cast<__half2*>(&c[mt][5][hf]));
        __half2 m67 = __hmax2(*reinterpret_cast<__half2*>(&c[mt][6][hf]),
                              *reinterpret_cast<__half2*>(&c[mt][7][hf]));
        __half2 m = __hmax2(__hmax2(m01, m23), __hmax2(m45, m67));
        __half hm = __hmax(__low2half(m), __high2half(m));
        hmx[lr] = hm;
        float dv = __fmul_rn(-2.0f, __half2float(hm));
        dv = fminf(dv, __shfl_xor_sync(FULL, dv, 1));
        dv = fminf(dv, __shfl_xor_sync(FULL, dv, 2));
        if (m4 == 0) {
            int row = mw * 64 + mt * 16 + hf * 8 + g;
            srm[row * 2 + nw] = dv;
        }
    }
    __syncthreads();
    {
        // 256 threads cover 256 rows exactly
        float r0 = srm[tid * 2], r1 = srm[tid * 2 + 1];
        sthr[tid] = fminf(r0, r1) + MARGIN;
        scnt[tid] = 0;
        sv[tid * 4 + 0] = 1e30f; sv[tid * 4 + 1] = 1e30f;
        sv[tid * 4 + 2] = 1e30f; sv[tid * 4 + 3] = 1e30f;
        si[tid * 4 + 0] = 0; si[tid * 4 + 1] = 0;
        si[tid * 4 + 2] = 0; si[tid * 4 + 3] = 0;
    }
    __syncthreads();

    // ---- Phase B: threshold collect (fast path skips whole row-part) ----
    #pragma unroll
    for (int lr = 0; lr < 8; lr++) {
        const int mt = lr >> 1, hf = lr & 1;
        int row = mw * 64 + mt * 16 + hf * 8 + g;
        float thr = sthr[row];
        __half T = __float2half_rd(__fmul_rn(-0.5f, thr));   // superset capture
        if (__hge(hmx[lr], T)) {
            #pragma unroll
            for (int nt = 0; nt < 8; nt++) {
                float2 f = __half22float2(*reinterpret_cast<__half2*>(&c[mt][nt][hf]));
                int j0 = colBase + nw * 64 + nt * 8 + m4 * 2;
                float dv0 = __fmul_rn(-2.0f, f.x);
                float dv1 = __fmul_rn(-2.0f, f.y);
                if (dv0 <= thr) {
                    int s = atomicAdd(&scnt[row], 1);
                    if (s < 4) { sv[row * 4 + s] = dv0; si[row * 4 + s] = j0; }
                }
                if (dv1 <= thr) {
                    int s = atomicAdd(&scnt[row], 1);
                    if (s < 4) { sv[row * 4 + s] = dv1; si[row * 4 + s] = j0 + 1; }
                }
            }
        }
    }
    __syncthreads();

    {
        int n = rowBase + tid;
        g_tv[(size_t)n * NTILES + blockIdx.y] =
            make_float4(sv[tid * 4], sv[tid * 4 + 1], sv[tid * 4 + 2], sv[tid * 4 + 3]);
        g_ti[(size_t)n * NTILES + blockIdx.y] =
            make_int4(si[tid * 4], si[tid * 4 + 1], si[tid * 4 + 2], si[tid * 4 + 3]);
    }
}

// ---------------- K3: exact rescore, warp-cooperative dots ----------------
__global__ __launch_bounds__(128) void k_rescore(const float* __restrict__ emb,
                                                 float* __restrict__ idx_out_f) {
    const unsigned FULL = 0xffffffffu;
    int wid = threadIdx.x >> 5, lid = threadIdx.x & 31;
    int n = blockIdx.x * 4 + wid;
    const float4* tv = g_tv + (size_t)n * NTILES;
    const int4*   ti = g_ti + (size_t)n * NTILES;

    const float* xr = g_xt + (size_t)n * CDIM;
    float4 x0 = *reinterpret_cast<const float4*>(&xr[lid * 8]);
    float4 x1 = *reinterpret_cast<const float4*>(&xr[lid * 8 + 4]);
    const float S = g_rownorm[n];

    float ev[8]; int ei[8];
    #pragma unroll
    for (int q = 0; q < 8; q++) {
        int e = q * 32 + lid;                      // entry 0..255
        float4 v4 = tv[e >> 2];
        int4   i4 = ti[e >> 2];
        int rk = e & 3;
        ev[q] = (rk == 0) ? v4.x : (rk == 1) ? v4.y : (rk == 2) ? v4.z : v4.w;
        ei[q] = (rk == 0) ? i4.x : (rk == 1) ? i4.y : (rk == 2) ? i4.z : i4.w;
    }
    float m = 1e30f;
    #pragma unroll
    for (int q = 0; q < 8; q++) m = fminf(m, ev[q]);
    #pragma unroll
    for (int off = 16; off > 0; off >>= 1)
        m = fminf(m, __shfl_xor_sync(FULL, m, off));
    const float thr = m + MARGIN;

    float best = 1e30f; int bj = 0x7fffffff;
    #pragma unroll
    for (int q = 0; q < 8; q++) {
        unsigned mask = __ballot_sync(FULL, ev[q] <= thr);
        while (mask) {
            int src = __ffs(mask) - 1;
            mask &= mask - 1;
            int j = __shfl_sync(FULL, ei[q], src);
            const float* er = emb + (size_t)j * CDIM;
            float4 e0 = *reinterpret_cast<const float4*>(&er[lid * 8]);
            float4 e1 = *reinterpret_cast<const float4*>(&er[lid * 8 + 4]);
            float dot = 0.0f;
            dot = __fmaf_rn(x0.x, e0.x, dot);
            dot = __fmaf_rn(x0.y, e0.y, dot);
            dot = __fmaf_rn(x0.z, e0.z, dot);
            dot = __fmaf_rn(x0.w, e0.w, dot);
            dot = __fmaf_rn(x1.x, e1.x, dot);
            dot = __fmaf_rn(x1.y, e1.y, dot);
            dot = __fmaf_rn(x1.z, e1.z, dot);
            dot = __fmaf_rn(x1.w, e1.w, dot);
            #pragma unroll
            for (int off = 16; off > 0; off >>= 1)
                dot = __fadd_rn(dot, __shfl_xor_sync(FULL, dot, off));
            float d = __fadd_rn(S, -__fmul_rn(2.0f, dot));
            if (d < best || (d == best && j < bj)) { best = d; bj = j; }
        }
    }
    if (lid == 0) {
        g_idx[n] = bj;
        idx_out_f[n] = (float)bj;
    }
}

// ---------------- K4: transpose-free output + loss partials ----------------
__global__ __launch_bounds__(256) void k_output(const float* __restrict__ z,
                                                const float* __restrict__ emb,
                                                float* __restrict__ out) {
    __shared__ double sred[8];
    int b = blockIdx.z, c0 = blockIdx.y * 32, hw0 = blockIdx.x * 256;
    int tx = threadIdx.x, ty = threadIdx.y;        // (64, 4)
    int hw = hw0 + tx * 4;
    int n0 = b * HW + hw;
    int4 id4 = *reinterpret_cast<const int4*>(&g_idx[n0]);

    double acc = 0.0;
    #pragma unroll
    for (int i = 0; i < 8; i++) {
        int c = c0 + ty + i * 4;
        size_t zoff = ((size_t)(b * CDIM + c)) * HW + hw;
        float4 zv = *reinterpret_cast<const float4*>(&z[zoff]);
        float q0 = emb[(size_t)id4.x * CDIM + c];
        float q1 = emb[(size_t)id4.y * CDIM + c];
        float q2 = emb[(size_t)id4.z * CDIM + c];
        float q3 = emb[(size_t)id4.w * CDIM + c];
        float t0 = __fsub_rn(q0, zv.x);
        float t1 = __fsub_rn(q1, zv.y);
        float t2 = __fsub_rn(q2, zv.z);
        float t3 = __fsub_rn(q3, zv.w);
        float4 o;
        o.x = __fadd_rn(zv.x, t0);
        o.y = __fadd_rn(zv.y, t1);
        o.z = __fadd_rn(zv.z, t2);
        o.w = __fadd_rn(zv.w, t3);
        *reinterpret_cast<float4*>(&out[zoff]) = o;
        acc += (double)__fmul_rn(t0, t0);
        acc += (double)__fmul_rn(t1, t1);
        acc += (double)__fmul_rn(t2, t2);
        acc += (double)__fmul_rn(t3, t3);
    }

    int tid = ty * 64 + tx;
    #pragma unroll
    for (int off = 16; off > 0; off >>= 1)
        acc += __shfl_down_sync(0xffffffffu, acc, off);
    if ((tid & 31) == 0) sred[tid >> 5] = acc;
    __syncthreads();
    if (tid == 0) {
        double s = 0.0;
        #pragma unroll
        for (int w = 0; w < 8; w++) s += sred[w];
        g_partial[blockIdx.x + 4 * (blockIdx.y + 8 * blockIdx.z)] = s;
    }
}

// ---------------- K5: final loss reduce ----------------
__global__ void k_loss(float* __restrict__ out_loss) {
    __shared__ double sred[256];
    int tid = threadIdx.x;
    double acc = 0.0;
    for (int q = tid; q < 512; q += 256) acc += g_partial[q];
    sred[tid] = acc;
    __syncthreads();
    for (int s = 128; s > 0; s >>= 1) {
        if (tid < s) sred[tid] += sred[tid + s];
        __syncthreads();
    }
    if (tid == 0) {
        float m = (float)(sred[0] / (double)OUT_N);
        out_loss[0] = __fadd_rn(m, __fmul_rn(0.25f, m));
    }
}

// ---------------- entry ----------------
extern "C" void kernel_launch(void* const* d_in, const int* in_sizes, int n_in,
                              void* d_out, int out_size) {
    const float* z   = (const float*)d_in[0];
    const float* emb = (const float*)d_in[1];
    float* out    = (float*)d_out;
    float* loss_p = out + OUT_N;
    float* idx_p  = out + OUT_N + 1;

    cudaFuncSetAttribute(k_gemm_coarse,
                         cudaFuncAttributeMaxDynamicSharedMemorySize, GEMM_SMEM);

    k_transpose<<<dim3(32, 8, 16), dim3(32, 8)>>>(z);
    k_ehf<<<(KEMB * CDIM / 4) / 256, 256>>>(emb);
    k_rownorm<<<NROWS / 8, dim3(32, 8)>>>();
    k_gemm_coarse<<<dim3(NROWS / 256, KEMB / 128), 256, GEMM_SMEM>>>();
    k_rescore<<<NROWS / 4, 128>>>(emb, idx_p);
    k_output<<<dim3(4, 8, 16), dim3(64, 4)>>>(z, emb, out);
    k_loss<<<1, 256>>>(loss_p);
}